// round 11
// baseline (speedup 1.0000x reference)
#include <cuda_runtime.h>

// LightConv depthwise causal conv, GB300 sm_103a — pure register pipeline.
// x: [T=4096, B=8, C=1024] fp32, weight: [H=16, K=31] fp32 (softmax over K per head).
// out[t,b,c] = sum_k softmax(w)[c/64,k] * x[t-30+k, b, c]   (x = 0 for t < 0)
//
// Architecture (validated R9): per thread one float2 column; 32-slot rolling
// accumulator ring (&31 indexing, slot g&31 init'd 30 steps early by tap w[0],
// drained at step g by tap w[30]); 8-slot register prefetch ring (distance 8);
// __launch_bounds__(128,3) -> 3 blocks/SM, 12 warps/SM; TT=320, grid (32,13).
//
// R10 changes: (a) hot-loop guards removed — stage variants are compile-time
// specialized (warm-up guarded only for tile 0; main stages unguarded; last
// stage drops its 8 dead trailing refills statically). (b) stores use
// st.global.cs (streaming, evict-first) to preserve L2 for halo re-reads.

#define T_DIM   4096
#define B_DIM   8
#define C_DIM   1024
#define K_TAPS  31
#define SLOTS   32                        // accumulator ring size (power of 2)
#define PF      8                         // prefetch ring size, divides SLOTS
#define ROW     ((B_DIM * C_DIM) / 2)     // u64 per t-row = 4096
#define BC2     ((B_DIM * C_DIM) / 2)
#define THREADS 128
#define NJ      10                        // store stages per tile
#define TT      (NJ * SLOTS)              // 320 outputs per tile
#define GRIDY   13                        // last tile clamped to t0 = 3776

typedef unsigned long long u64;
typedef unsigned int u32;

__device__ __forceinline__ u64 ffma2(u64 a, u64 b, u64 c) {
    u64 d;
    asm("fma.rn.f32x2 %0, %1, %2, %3;" : "=l"(d) : "l"(a), "l"(b), "l"(c));
    return d;
}
__device__ __forceinline__ u64 fmul2(u64 a, u64 b) {
    u64 d;
    asm("mul.rn.f32x2 %0, %1, %2;" : "=l"(d) : "l"(a), "l"(b));
    return d;
}
__device__ __forceinline__ void stcs64(u64* p, u64 v) {
    asm volatile("st.global.cs.b64 [%0], %1;" :: "l"(p), "l"(v) : "memory");
}

// One 32-step stage. STON: emit stores. GUARD: predicate refills on tr>=0
// (only tile 0's warm-up needs it). TRIM: drop the last PF refills (final
// stage; those would feed a nonexistent next stage / read OOB).
template <bool STON, bool GUARD, bool TRIM>
__device__ __forceinline__ void stage_body(
    u64 (&acc)[SLOTS], u64 (&xb)[PF], const u64 (&wv)[K_TAPS],
    const u64* __restrict__ pfp, u64* __restrict__ q, int rowbase)
{
#pragma unroll
    for (int u = 0; u < SLOTS; u++) {
        u64 xv = xb[u & (PF - 1)];
        // refill row rowbase+u+PF into the just-freed prefetch slot
        if (!TRIM || u < SLOTS - PF) {
            if (GUARD) {
                const int tr = rowbase + u + PF;
                xb[u & (PF - 1)] = (tr >= 0) ? pfp[(long)u * ROW] : 0ull;
            } else {
                xb[u & (PF - 1)] = pfp[(long)u * ROW];
            }
        }
        // drain slot u: out[rowbase+u] = acc + w[30]*x[rowbase+u]
        u64 o = ffma2(wv[30], xv, acc[u]);
        if (STON) stcs64(q + (long)u * ROW, o);
        // scatter middle taps (compile-time ring indices)
#pragma unroll
        for (int d = 1; d <= 29; d++) {
            acc[(u + d) & (SLOTS - 1)] =
                ffma2(wv[30 - d], xv, acc[(u + d) & (SLOTS - 1)]);
        }
        // first tap initializes the slot for out[rowbase+u+30]
        acc[(u + 30) & (SLOTS - 1)] = fmul2(wv[0], xv);
    }
}

__global__ __launch_bounds__(THREADS, 3) void lightconv_kernel(
    const float* __restrict__ x, const float* __restrict__ wg,
    float* __restrict__ out)
{
    const int tid = threadIdx.x;
    const int bc2 = blockIdx.x * THREADS + tid;            // this thread's u64 column
    const int by  = blockIdx.y;
    const int t0  = (by < GRIDY - 1) ? by * TT : (T_DIM - TT);  // 3776 % 32 == 0
    const int h   = ((bc2 * 2) & (C_DIM - 1)) >> 6;        // head (warp-uniform)

    // ---- per-thread softmax of this head's 31 taps, packed {w,w} ----
    float wf[K_TAPS];
    float mx = -3.402823466e38f;
#pragma unroll
    for (int k = 0; k < K_TAPS; k++) {
        wf[k] = __ldg(wg + h * K_TAPS + k);
        mx = fmaxf(mx, wf[k]);
    }
    float ssum = 0.0f;
#pragma unroll
    for (int k = 0; k < K_TAPS; k++) { wf[k] = expf(wf[k] - mx); ssum += wf[k]; }
    const float inv = 1.0f / ssum;
    u64 wv[K_TAPS];
#pragma unroll
    for (int k = 0; k < K_TAPS; k++) {
        u32 b = __float_as_uint(wf[k] * inv);
        wv[k] = ((u64)b << 32) | (u64)b;
    }

    const u64* __restrict__ px = (const u64*)x + bc2;      // per-thread column
    u64* __restrict__ po       = (u64*)out + bc2;
    const int s0 = t0 - SLOTS;                             // first warm-up row

    u64 acc[SLOTS];
#pragma unroll
    for (int u = 0; u < SLOTS; u++) acc[u] = 0ull;

    u64 xb[PF];

    if (t0 == 0) {
        // tile 0: rows s0..s0+7 are negative -> zero; warm-up refills guarded
#pragma unroll
        for (int p = 0; p < PF; p++) xb[p] = 0ull;
        stage_body<false, true, false>(acc, xb, wv,
                                       px + (long)(s0 + PF) * ROW,
                                       po /*unused*/, s0);
    } else {
        // interior tiles: everything in-bounds, no guards anywhere
#pragma unroll
        for (int p = 0; p < PF; p++) xb[p] = px[(long)(s0 + p) * ROW];
        stage_body<false, false, false>(acc, xb, wv,
                                        px + (long)(s0 + PF) * ROW,
                                        po /*unused*/, s0);
    }

    // ---- main stages j = 1 .. NJ-1: unguarded refills + streaming stores ----
#pragma unroll 1
    for (int j = 1; j < NJ; j++) {
        const int rowbase = s0 + j * SLOTS;
        stage_body<true, false, false>(acc, xb, wv,
                                       px + (long)(rowbase + PF) * ROW,
                                       po + (long)rowbase * ROW, rowbase);
    }

    // ---- last stage: stores on, trailing PF refills dropped statically ----
    {
        const int rowbase = s0 + NJ * SLOTS;               // = t0 + TT - 32
        stage_body<true, false, true>(acc, xb, wv,
                                      px + (long)(rowbase + PF) * ROW,
                                      po + (long)rowbase * ROW, rowbase);
    }
}

extern "C" void kernel_launch(void* const* d_in, const int* in_sizes, int n_in,
                              void* d_out, int out_size) {
    const float* x = (const float*)d_in[0];
    const float* w = (const float*)d_in[1];
    if (n_in >= 2 && in_sizes[0] < in_sizes[1]) {   // robustness: x is the big tensor
        x = (const float*)d_in[1];
        w = (const float*)d_in[0];
    }
    dim3 grid(BC2 / THREADS, GRIDY);                // (32, 13) = 416 blocks, one wave
    lightconv_kernel<<<grid, THREADS>>>(x, w, (float*)d_out);
}